// round 1
// baseline (speedup 1.0000x reference)
#include <cuda_runtime.h>
#include <cuda_bf16.h>
#include <math.h>

// Problem constants
#define B_  16
#define C_  4
#define J_  19
#define T_  256
#define S_  10
#define D1_ 64
#define D2_ 64
#define O_  64
#define NCH (C_*J_*T_)          // 19456 BN channels
#define NPIX (B_*T_*S_)         // 40960 pixels
#define EPSV 1e-5f

// ---------------- device scratch (no runtime allocation allowed) -------------
__device__ float g_bn_a[NCH];
__device__ float g_bn_b[NCH];
__device__ float g_w1t[C_*64];      // w1t[c][d]
__device__ float g_w2t[64*64];      // w2t[k][d]
__device__ float g_Mt[64*64];       // Mt[b][a] = M[a][b] = sum_s ws1[s][a]*ws2[s][b]
__device__ float g_v[64];           // v[b] = sum_s ws2[s][b]*bs1[s]

// ---------------- kernel 1: BN statistics -> per-channel affine --------------
__global__ void bn_stats_kernel(const float* __restrict__ x,
                                const float* __restrict__ gamma,
                                const float* __restrict__ beta) {
    int ch = blockIdx.x * 8 + (threadIdx.x >> 5);
    if (ch >= NCH) return;
    int lane = threadIdx.x & 31;
    float s = 0.f, ss = 0.f;
    // x viewed as (B, NCH, S): element = x[(b*NCH + ch)*S + s]
    for (int e = lane; e < B_ * S_; e += 32) {
        int b = e / S_, si = e % S_;
        float v = x[(b * NCH + ch) * S_ + si];
        s += v; ss += v * v;
    }
    #pragma unroll
    for (int off = 16; off; off >>= 1) {
        s  += __shfl_xor_sync(0xffffffffu, s,  off);
        ss += __shfl_xor_sync(0xffffffffu, ss, off);
    }
    if (lane == 0) {
        const float inv_n = 1.f / (float)(B_ * S_);
        float mean = s * inv_n;
        float var  = ss * inv_n - mean * mean;
        float a = gamma[ch] * rsqrtf(var + EPSV);
        g_bn_a[ch] = a;
        g_bn_b[ch] = beta[ch] - mean * a;
    }
}

// ---------------- kernel 2: precompute M, v, transposed weights --------------
__global__ void setup_kernel(const float* __restrict__ w1,
                             const float* __restrict__ w2,
                             const float* __restrict__ ws1,
                             const float* __restrict__ bs1,
                             const float* __restrict__ ws2) {
    int idx = blockIdx.x * blockDim.x + threadIdx.x;   // grid covers 4096
    if (idx < 4096) {
        int b = idx >> 6, a = idx & 63;
        float acc = 0.f;
        #pragma unroll 4
        for (int s = 0; s < 128; ++s)
            acc += ws1[s * 64 + a] * ws2[s * 64 + b];
        g_Mt[b * 64 + a] = acc;                        // Mt[b][a]
        // w2t[k][d] = w2[d][k];  idx = k*64+d
        g_w2t[idx] = w2[(idx & 63) * 64 + (idx >> 6)];
    }
    if (idx < C_ * 64) {                               // w1t[c][d] = w1[d][c]
        g_w1t[idx] = w1[(idx & 63) * C_ + (idx >> 6)];
    }
    if (idx < 64) {
        float acc = 0.f;
        #pragma unroll 4
        for (int s = 0; s < 128; ++s)
            acc += ws2[s * 64 + idx] * bs1[s];
        g_v[idx] = acc;
    }
}

// ---------------- kernel 3: fused per-pixel pipeline --------------------------
// smem layout (floats)
#define OFF_W1T   0        // 256
#define OFF_B1    256      // 64
#define OFF_W2T   320      // 4096
#define OFF_B2    4416     // 64
#define OFF_MT    4480     // 4096
#define OFF_W     8576     // 4096  (W[c][o], already inner-major)
#define OFF_V     12672    // 64
#define OFF_XN    12736    // 4*20
#define OFF_H1    12816    // 64*20
#define OFF_H     14096    // 64*20
#define OFF_G     15376    // 64*20
#define OFF_PT    16656    // 19*64
#define OFF_LT    17872    // 19*20
#define OFF_VH    18252    // 19
#define SMEM_FLOATS 18272
#define SMEM_BYTES (SMEM_FLOATS * 4)

__global__ __launch_bounds__(256, 3)
void geo_gcn_main_kernel(const float* __restrict__ x,
                         const float* __restrict__ b1,
                         const float* __restrict__ b2,
                         const float* __restrict__ W,
                         float* __restrict__ out) {
    extern __shared__ float sm[];
    float* sw1t = sm + OFF_W1T;
    float* sb1  = sm + OFF_B1;
    float* sw2t = sm + OFF_W2T;
    float* sb2  = sm + OFF_B2;
    float* sMt  = sm + OFF_MT;
    float* sW   = sm + OFF_W;
    float* sv   = sm + OFF_V;
    float* sxn  = sm + OFF_XN;
    float* sh1  = sm + OFF_H1;
    float* sH   = sm + OFF_H;
    float* sG   = sm + OFF_G;
    float* sPt  = sm + OFF_PT;
    float* sLT  = sm + OFF_LT;
    float* svh  = sm + OFF_VH;

    const int tid = threadIdx.x;

    // cooperative weight load (all L2-resident)
    #pragma unroll
    for (int i = 0; i < 16; ++i) {
        int p = i * 256 + tid;
        sw2t[p] = g_w2t[p];
        sMt[p]  = g_Mt[p];
        sW[p]   = W[p];
    }
    sw1t[tid] = g_w1t[tid];
    if (tid < 64) { sb1[tid] = b1[tid]; sb2[tid] = b2[tid]; sv[tid] = g_v[tid]; }

    const int bid = blockIdx.x;
    const int s_i = bid % S_;
    const int t_i = (bid / S_) % T_;
    const int b_i = bid / (S_ * T_);

    // Phase A: load + BN-normalize the 4x19 input slice for this pixel
    if (tid < C_ * J_) {
        int c = tid / J_, j = tid % J_;
        int ch = (c * J_ + j) * T_ + t_i;
        float v = x[(b_i * NCH + ch) * S_ + s_i];
        sxn[c * 20 + j] = v * g_bn_a[ch] + g_bn_b[ch];
    }
    __syncthreads();

    const int d  = tid & 63;
    const int jg = tid >> 6;
    const int j0 = jg * 5;
    const int nj = (jg < 3) ? 5 : 4;   // j0=15 covers j=15..18

    // Phase B: h1[d][j] = relu(W1 xn + b1)
    {
        float acc[5];
        float bb = sb1[d];
        #pragma unroll
        for (int i = 0; i < 5; ++i) acc[i] = bb;
        #pragma unroll
        for (int c = 0; c < C_; ++c) {
            float w = sw1t[c * 64 + d];
            #pragma unroll
            for (int i = 0; i < 5; ++i) acc[i] += w * sxn[c * 20 + j0 + i];
        }
        for (int i = 0; i < nj; ++i) sh1[d * 20 + j0 + i] = fmaxf(acc[i], 0.f);
    }
    __syncthreads();

    // Phase C: H[d][j] = relu(W2 h1 + b2)
    {
        float acc[5];
        float bb = sb2[d];
        #pragma unroll
        for (int i = 0; i < 5; ++i) acc[i] = bb;
        #pragma unroll 8
        for (int k = 0; k < 64; ++k) {
            float w = sw2t[k * 64 + d];
            #pragma unroll
            for (int i = 0; i < 5; ++i) acc[i] += w * sh1[k * 20 + j0 + i];
        }
        for (int i = 0; i < nj; ++i) sH[d * 20 + j0 + i] = fmaxf(acc[i], 0.f);
    }
    __syncthreads();

    // Phase D: G[a][k] = sum_b M[a][b] H[b][k]   (a=d, cols=k)
    {
        float acc[5] = {0.f, 0.f, 0.f, 0.f, 0.f};
        #pragma unroll 8
        for (int k = 0; k < 64; ++k) {
            float w = sMt[k * 64 + d];
            #pragma unroll
            for (int i = 0; i < 5; ++i) acc[i] += w * sH[k * 20 + j0 + i];
        }
        for (int i = 0; i < nj; ++i) sG[d * 20 + j0 + i] = acc[i];
    }
    __syncthreads();

    // Phase E: Pt[k][o] = sum_c W[c][o] H[c][k]    (o=d, cols=k)
    {
        float acc[5] = {0.f, 0.f, 0.f, 0.f, 0.f};
        #pragma unroll 8
        for (int c = 0; c < 64; ++c) {
            float w = sW[c * 64 + d];
            #pragma unroll
            for (int i = 0; i < 5; ++i) acc[i] += w * sH[c * 20 + j0 + i];
        }
        for (int i = 0; i < nj; ++i) sPt[(j0 + i) * 64 + d] = acc[i];
    }
    __syncthreads();

    // Phase F: logits[j][k] = sum_a H[a][j] G[a][k]  (stored transposed LT[k][j])
    // plus vh[k] = sum_b v[b] H[b][k]  (softmax-relevant bias term)
    {
        {   // pass 1: outputs 0..255
            int k = tid / J_, jj = tid % J_;
            float acc = 0.f;
            #pragma unroll 8
            for (int a = 0; a < 64; ++a)
                acc += sH[a * 20 + jj] * sG[a * 20 + k];
            sLT[k * 20 + jj] = acc;
        }
        if (tid < 105) {   // pass 2: outputs 256..360
            int idx = 256 + tid;
            int k = idx / J_, jj = idx % J_;
            float acc = 0.f;
            #pragma unroll 8
            for (int a = 0; a < 64; ++a)
                acc += sH[a * 20 + jj] * sG[a * 20 + k];
            sLT[k * 20 + jj] = acc;
        } else if (tid < 105 + J_) {   // vh
            int k = tid - 105;
            float acc = 0.f;
            #pragma unroll 8
            for (int b = 0; b < 64; ++b)
                acc += sv[b] * sH[b * 20 + k];
            svh[k] = acc;
        }
    }
    __syncthreads();

    // softmax over k per row j (19 lanes of warp 0), att written back into sLT
    if (tid < J_) {
        float l[J_];
        float mx = -1e30f;
        #pragma unroll
        for (int k = 0; k < J_; ++k) {
            l[k] = sLT[k * 20 + tid] + svh[k];
            mx = fmaxf(mx, l[k]);
        }
        float sum = 0.f;
        #pragma unroll
        for (int k = 0; k < J_; ++k) { l[k] = __expf(l[k] - mx); sum += l[k]; }
        float inv = 1.f / sum;
        #pragma unroll
        for (int k = 0; k < J_; ++k) sLT[k * 20 + tid] = l[k] * inv;
    }
    __syncthreads();

    // Final: out[o][j] = sum_k att[j][k] * Pt[k][o]     (o=d)
    {
        float acc[5] = {0.f, 0.f, 0.f, 0.f, 0.f};
        #pragma unroll
        for (int k = 0; k < J_; ++k) {
            float p = sPt[k * 64 + d];
            #pragma unroll
            for (int i = 0; i < 5; ++i) acc[i] += p * sLT[k * 20 + j0 + i];
        }
        int base = ((b_i * O_ + d) * J_) * (T_ * S_) + t_i * S_ + s_i;
        for (int i = 0; i < nj; ++i)
            out[base + (j0 + i) * (T_ * S_)] = acc[i];
    }
}

// ------------------------------ launcher --------------------------------------
extern "C" void kernel_launch(void* const* d_in, const int* in_sizes, int n_in,
                              void* d_out, int out_size) {
    const float* x     = (const float*)d_in[0];
    const float* gamma = (const float*)d_in[1];
    const float* beta  = (const float*)d_in[2];
    const float* w1    = (const float*)d_in[3];
    const float* b1    = (const float*)d_in[4];
    const float* w2    = (const float*)d_in[5];
    const float* b2    = (const float*)d_in[6];
    const float* ws1   = (const float*)d_in[7];
    const float* bs1   = (const float*)d_in[8];
    const float* ws2   = (const float*)d_in[9];
    // d_in[10] = bs2 (unused: softmax-invariant), d_in[11] = W
    const float* W     = (const float*)d_in[11];
    float* out = (float*)d_out;

    cudaFuncSetAttribute(geo_gcn_main_kernel,
                         cudaFuncAttributeMaxDynamicSharedMemorySize, SMEM_BYTES);

    bn_stats_kernel<<<NCH / 8, 256>>>(x, gamma, beta);
    setup_kernel<<<16, 256>>>(w1, w2, ws1, bs1, ws2);
    geo_gcn_main_kernel<<<NPIX, 256, SMEM_BYTES>>>(x, b1, b2, W, out);
}

// round 2
// speedup vs baseline: 2.1694x; 2.1694x over previous
#include <cuda_runtime.h>
#include <cuda_bf16.h>
#include <math.h>

// Problem constants
#define B_  16
#define C_  4
#define J_  19
#define T_  256
#define S_  10
#define NCH (C_*J_*T_)          // 19456 BN channels
#define NPIX (B_*T_*S_)         // 40960 pixels
#define EPSV 1e-5f

#define PPB 4                   // pixels per block
#define NC  80                  // columns per block (4 pixels x 20)
#define AST 85                  // activation row stride (bank-conflict padding)

// ---------------- device scratch ----------------------------------------------
__device__ float g_bn_a[NCH];
__device__ float g_bn_b[NCH];
__device__ float g_w1t[C_*64];      // w1t[c][d]
__device__ float g_w2t[64*64];      // w2t[k][d]
__device__ float g_Mt[64*64];       // Mt[b][a] = M[a][b]
__device__ float g_v[64];           // v[b] = sum_s ws2[s][b]*bs1[s]

// ---------------- kernel 1: BN statistics -> per-channel affine ---------------
__global__ void bn_stats_kernel(const float* __restrict__ x,
                                const float* __restrict__ gamma,
                                const float* __restrict__ beta) {
    int ch = blockIdx.x * 8 + (threadIdx.x >> 5);
    if (ch >= NCH) return;
    int lane = threadIdx.x & 31;
    float s = 0.f, ss = 0.f;
    for (int e = lane; e < B_ * S_; e += 32) {
        int b = e / S_, si = e % S_;
        float v = x[(b * NCH + ch) * S_ + si];
        s += v; ss += v * v;
    }
    #pragma unroll
    for (int off = 16; off; off >>= 1) {
        s  += __shfl_xor_sync(0xffffffffu, s,  off);
        ss += __shfl_xor_sync(0xffffffffu, ss, off);
    }
    if (lane == 0) {
        const float inv_n = 1.f / (float)(B_ * S_);
        float mean = s * inv_n;
        float var  = ss * inv_n - mean * mean;
        float a = gamma[ch] * rsqrtf(var + EPSV);
        g_bn_a[ch] = a;
        g_bn_b[ch] = beta[ch] - mean * a;
    }
}

// ---------------- kernel 2: precompute M, v, transposed weights ---------------
__global__ void setup_kernel(const float* __restrict__ w1,
                             const float* __restrict__ w2,
                             const float* __restrict__ ws1,
                             const float* __restrict__ bs1,
                             const float* __restrict__ ws2) {
    int idx = blockIdx.x * blockDim.x + threadIdx.x;
    if (idx < 4096) {
        int b = idx >> 6, a = idx & 63;
        float acc = 0.f;
        #pragma unroll 4
        for (int s = 0; s < 128; ++s)
            acc += ws1[s * 64 + a] * ws2[s * 64 + b];
        g_Mt[b * 64 + a] = acc;
        g_w2t[idx] = w2[(idx & 63) * 64 + (idx >> 6)];
    }
    if (idx < C_ * 64) g_w1t[idx] = w1[(idx & 63) * C_ + (idx >> 6)];
    if (idx < 64) {
        float acc = 0.f;
        #pragma unroll 4
        for (int s = 0; s < 128; ++s)
            acc += ws2[s * 64 + idx] * bs1[s];
        g_v[idx] = acc;
    }
}

// ---------------- smem layout (float offsets) ----------------------------------
#define OFF_W1T   0        // 256
#define OFF_B1    256      // 64
#define OFF_B2    320      // 64
#define OFF_V     384      // 64
#define OFF_W2T   448      // 4096 (16B aligned)
#define OFF_MT    4544     // 4096 (aliased later: LT + vh)
#define OFF_WW    8640     // 4096
#define OFF_PT    12736    // 4*19*64 = 4864
#define OFF_XN    17600    // 4*85  = 340
#define OFF_H1G   17940    // 64*85 = 5440 (h1, later G)
#define OFF_H     23380    // 64*85 = 5440
#define SMEM_FLOATS 28820
#define SMEM_BYTES (SMEM_FLOATS * 4)
// aliases inside dead Mt region (Mt unused after phase D+E):
#define OFF_LT    OFF_MT          // 4*20*20 = 1600
#define OFF_VH    (OFF_MT + 1600) // 4*20    = 80

__global__ __launch_bounds__(256, 2)
void geo_gcn_main_kernel(const float* __restrict__ x,
                         const float* __restrict__ b1g,
                         const float* __restrict__ b2g,
                         const float* __restrict__ Wg,
                         float* __restrict__ out) {
    extern __shared__ float sm[];
    const int tid = threadIdx.x;

    // ---- cooperative weight load (all L2-resident) ----
    #pragma unroll
    for (int i = 0; i < 16; ++i) {
        int p = i * 256 + tid;
        sm[OFF_W2T + p] = g_w2t[p];
        sm[OFF_MT  + p] = g_Mt[p];
        sm[OFF_WW  + p] = Wg[p];
    }
    sm[OFF_W1T + tid] = g_w1t[tid];
    if (tid < 64) {
        sm[OFF_B1 + tid] = b1g[tid];
        sm[OFF_B2 + tid] = b2g[tid];
        sm[OFF_V  + tid] = g_v[tid];
    }

    const int pix0 = blockIdx.x * PPB;

    // ---- Phase A: load + BN the 4 pixels' (4 x 19) slices, pad cols -> 0 ----
    for (int idx = tid; idx < C_ * AST; idx += 256) {
        int c = idx / AST, col = idx % AST;
        float v = 0.f;
        if (col < NC) {
            int p = col / 20, j = col % 20;
            if (j < J_) {
                int pix = pix0 + p;
                int s  = pix % S_;
                int tt = (pix / S_) & (T_ - 1);
                int bb = pix / (S_ * T_);
                int ch = (c * J_ + j) * T_ + tt;
                v = x[(bb * NCH + ch) * S_ + s] * g_bn_a[ch] + g_bn_b[ch];
            }
        }
        sm[OFF_XN + idx] = v;
    }
    __syncthreads();

    const int dg = tid & 15, cg = tid >> 4;
    const int d0 = dg * 4, col0 = cg * 5;
    const int mypix = cg >> 2;             // pixel for this thread's columns
    const int jloc0 = (cg & 3) * 5;        // local j of first column

    // ---- Phase B: h1 = relu(W1 xn + b1) ----
    {
        float4 bb = *(const float4*)&sm[OFF_B1 + d0];
        float acc[4][5];
        #pragma unroll
        for (int i = 0; i < 4; ++i)
            #pragma unroll
            for (int r = 0; r < 5; ++r) acc[i][r] = (&bb.x)[i];
        #pragma unroll
        for (int k = 0; k < C_; ++k) {
            float4 w = *(const float4*)&sm[OFF_W1T + k * 64 + d0];
            float a[5];
            #pragma unroll
            for (int r = 0; r < 5; ++r) a[r] = sm[OFF_XN + k * AST + col0 + r];
            #pragma unroll
            for (int i = 0; i < 4; ++i)
                #pragma unroll
                for (int r = 0; r < 5; ++r) acc[i][r] += (&w.x)[i] * a[r];
        }
        #pragma unroll
        for (int i = 0; i < 4; ++i)
            #pragma unroll
            for (int r = 0; r < 5; ++r)
                sm[OFF_H1G + (d0 + i) * AST + col0 + r] = fmaxf(acc[i][r], 0.f);
    }
    __syncthreads();

    // ---- Phase C: H = relu(W2 h1 + b2) ----
    {
        float4 bb = *(const float4*)&sm[OFF_B2 + d0];
        float acc[4][5];
        #pragma unroll
        for (int i = 0; i < 4; ++i)
            #pragma unroll
            for (int r = 0; r < 5; ++r) acc[i][r] = (&bb.x)[i];
        #pragma unroll 8
        for (int k = 0; k < 64; ++k) {
            float4 w = *(const float4*)&sm[OFF_W2T + k * 64 + d0];
            float a[5];
            #pragma unroll
            for (int r = 0; r < 5; ++r) a[r] = sm[OFF_H1G + k * AST + col0 + r];
            #pragma unroll
            for (int i = 0; i < 4; ++i)
                #pragma unroll
                for (int r = 0; r < 5; ++r) acc[i][r] += (&w.x)[i] * a[r];
        }
        #pragma unroll
        for (int i = 0; i < 4; ++i)
            #pragma unroll
            for (int r = 0; r < 5; ++r)
                sm[OFF_H + (d0 + i) * AST + col0 + r] = fmaxf(acc[i][r], 0.f);
    }
    __syncthreads();

    // ---- Phase D+E fused: G = M H  (into h1 buffer),  Pt[j][o] = W^T H ----
    {
        float accG[4][5], accP[4][5];
        #pragma unroll
        for (int i = 0; i < 4; ++i)
            #pragma unroll
            for (int r = 0; r < 5; ++r) { accG[i][r] = 0.f; accP[i][r] = 0.f; }
        #pragma unroll 8
        for (int k = 0; k < 64; ++k) {
            float4 wm = *(const float4*)&sm[OFF_MT + k * 64 + d0];
            float4 ww = *(const float4*)&sm[OFF_WW + k * 64 + d0];
            float a[5];
            #pragma unroll
            for (int r = 0; r < 5; ++r) a[r] = sm[OFF_H + k * AST + col0 + r];
            #pragma unroll
            for (int i = 0; i < 4; ++i)
                #pragma unroll
                for (int r = 0; r < 5; ++r) {
                    accG[i][r] += (&wm.x)[i] * a[r];
                    accP[i][r] += (&ww.x)[i] * a[r];
                }
        }
        #pragma unroll
        for (int i = 0; i < 4; ++i)
            #pragma unroll
            for (int r = 0; r < 5; ++r)
                sm[OFF_H1G + (d0 + i) * AST + col0 + r] = accG[i][r];
        #pragma unroll
        for (int r = 0; r < 5; ++r) {
            int j = jloc0 + r;
            if (j < J_) {
                float4 v4 = make_float4(accP[0][r], accP[1][r], accP[2][r], accP[3][r]);
                *(float4*)&sm[OFF_PT + (mypix * J_ + j) * 64 + d0] = v4;
            }
        }
    }
    __syncthreads();

    // ---- Phase F: logits LT[p][k][j] = sum_a H[a][j] G[a][k]; vh[p][k] ----
    if (tid < 200) {
        int p  = tid / 50;
        int q  = tid % 50;
        int j0 = (q / 5) * 2;
        int k0 = (q % 5) * 4;
        int hb = OFF_H   + p * 20;
        int gb = OFF_H1G + p * 20;
        float acc[2][4];
        #pragma unroll
        for (int r = 0; r < 2; ++r)
            #pragma unroll
            for (int i = 0; i < 4; ++i) acc[r][i] = 0.f;
        #pragma unroll 8
        for (int a = 0; a < 64; ++a) {
            float h0 = sm[hb + a * AST + j0];
            float h1 = sm[hb + a * AST + j0 + 1];
            float g[4];
            #pragma unroll
            for (int i = 0; i < 4; ++i) g[i] = sm[gb + a * AST + k0 + i];
            #pragma unroll
            for (int i = 0; i < 4; ++i) { acc[0][i] += h0 * g[i]; acc[1][i] += h1 * g[i]; }
        }
        #pragma unroll
        for (int i = 0; i < 4; ++i)
            #pragma unroll
            for (int r = 0; r < 2; ++r)
                sm[OFF_LT + (p * 20 + k0 + i) * 20 + (j0 + r)] = acc[r][i];
    } else {
        int idx = tid - 200;
        #pragma unroll
        for (int it = 0; it < 2; ++it, idx += 56) {
            if (idx < 80) {
                int p = idx / 20, k = idx % 20;
                float acc = 0.f;
                #pragma unroll 8
                for (int b = 0; b < 64; ++b)
                    acc += sm[OFF_V + b] * sm[OFF_H + b * AST + p * 20 + k];
                sm[OFF_VH + idx] = acc;
            }
        }
    }
    __syncthreads();

    // ---- softmax over k, per (pixel, j); att stored back into LT[p][k][j] ----
    if (tid < PPB * J_) {
        int p = tid / J_, j = tid % J_;
        float l[J_];
        float mx = -1e30f;
        #pragma unroll
        for (int k = 0; k < J_; ++k) {
            l[k] = sm[OFF_LT + (p * 20 + k) * 20 + j] + sm[OFF_VH + p * 20 + k];
            mx = fmaxf(mx, l[k]);
        }
        float sum = 0.f;
        #pragma unroll
        for (int k = 0; k < J_; ++k) { l[k] = __expf(l[k] - mx); sum += l[k]; }
        float inv = 1.f / sum;
        #pragma unroll
        for (int k = 0; k < J_; ++k)
            sm[OFF_LT + (p * 20 + k) * 20 + j] = l[k] * inv;
    }
    __syncthreads();

    // ---- Final: out[o][j] = sum_k att[j][k] * Pt[k][o] ----
    {
        float acc[4][5];
        #pragma unroll
        for (int i = 0; i < 4; ++i)
            #pragma unroll
            for (int r = 0; r < 5; ++r) acc[i][r] = 0.f;
        #pragma unroll 4
        for (int k = 0; k < J_; ++k) {
            float4 pt = *(const float4*)&sm[OFF_PT + (mypix * J_ + k) * 64 + d0];
            float a[5];
            #pragma unroll
            for (int r = 0; r < 5; ++r)
                a[r] = sm[OFF_LT + (mypix * 20 + k) * 20 + jloc0 + r];
            #pragma unroll
            for (int i = 0; i < 4; ++i)
                #pragma unroll
                for (int r = 0; r < 5; ++r) acc[i][r] += (&pt.x)[i] * a[r];
        }
        int pix = pix0 + mypix;
        int s  = pix % S_;
        int tt = (pix / S_) & (T_ - 1);
        int bb = pix / (S_ * T_);
        int base = ((bb * 64) * J_) * (T_ * S_) + tt * S_ + s;
        #pragma unroll
        for (int r = 0; r < 5; ++r) {
            int j = jloc0 + r;
            if (j < J_) {
                #pragma unroll
                for (int i = 0; i < 4; ++i)
                    out[base + ((d0 + i) * J_ + j) * (T_ * S_)] = acc[i][r];
            }
        }
    }
}

// ------------------------------ launcher --------------------------------------
extern "C" void kernel_launch(void* const* d_in, const int* in_sizes, int n_in,
                              void* d_out, int out_size) {
    const float* x     = (const float*)d_in[0];
    const float* gamma = (const float*)d_in[1];
    const float* beta  = (const float*)d_in[2];
    const float* w1    = (const float*)d_in[3];
    const float* b1    = (const float*)d_in[4];
    const float* w2    = (const float*)d_in[5];
    const float* b2    = (const float*)d_in[6];
    const float* ws1   = (const float*)d_in[7];
    const float* bs1   = (const float*)d_in[8];
    const float* ws2   = (const float*)d_in[9];
    // d_in[10] = bs2 (softmax-invariant), d_in[11] = W
    const float* W     = (const float*)d_in[11];
    float* out = (float*)d_out;

    cudaFuncSetAttribute(geo_gcn_main_kernel,
                         cudaFuncAttributeMaxDynamicSharedMemorySize, SMEM_BYTES);

    bn_stats_kernel<<<NCH / 8, 256>>>(x, gamma, beta);
    setup_kernel<<<16, 256>>>(w1, w2, ws1, bs1, ws2);
    geo_gcn_main_kernel<<<NPIX / PPB, 256, SMEM_BYTES>>>(x, b1, b2, W, out);
}

// round 3
// speedup vs baseline: 2.1920x; 1.0104x over previous
#include <cuda_runtime.h>
#include <cuda_bf16.h>
#include <math.h>

// Problem constants
#define B_  16
#define C_  4
#define J_  19
#define T_  256
#define S_  10
#define NCH (C_*J_*T_)          // 19456 BN channels
#define NPIX (B_*T_*S_)         // 40960 pixels
#define EPSV 1e-5f

#define PPB 4                   // pixels per block
#define NC  80                  // columns per block
#define AST 85                  // activation row stride (bank-conflict padding)

typedef unsigned long long u64;

// ---- f32x2 packed-math helpers (PTX-only; bit-identical to 2x FFMA) ----------
__device__ __forceinline__ u64 pk2(float a, float b) {
    u64 r; asm("mov.b64 %0, {%1, %2};" : "=l"(r) : "f"(a), "f"(b)); return r;
}
__device__ __forceinline__ u64 dup2(float a) {
    u64 r; asm("mov.b64 %0, {%1, %1};" : "=l"(r) : "f"(a)); return r;
}
__device__ __forceinline__ void upk2(u64 v, float& lo, float& hi) {
    asm("mov.b64 {%0, %1}, %2;" : "=f"(lo), "=f"(hi) : "l"(v));
}
__device__ __forceinline__ void fma2(u64& d, u64 a, u64 b) {
    asm("fma.rn.f32x2 %0, %1, %2, %0;" : "+l"(d) : "l"(a), "l"(b));
}
// 16B shared load -> two packed f32x2
__device__ __forceinline__ void lds_v2u64(const float* p, u64& lo, u64& hi) {
    unsigned a = (unsigned)__cvta_generic_to_shared(p);
    asm("ld.shared.v2.u64 {%0, %1}, [%2];" : "=l"(lo), "=l"(hi) : "r"(a));
}

// ---------------- device scratch ----------------------------------------------
__device__ float g_bn_a[NCH];
__device__ float g_bn_b[NCH];
__device__ float g_w1t[C_*64];      // w1t[c][d]
__device__ float g_w2t[64*64];      // w2t[k][d]
__device__ float g_Mt[64*64];       // Mt[b][a] = M[a][b]
__device__ float g_v[64];           // v[b] = sum_s ws2[s][b]*bs1[s]

// ---------------- kernel 1: BN statistics -> per-channel affine ---------------
__global__ void bn_stats_kernel(const float* __restrict__ x,
                                const float* __restrict__ gamma,
                                const float* __restrict__ beta) {
    int ch = blockIdx.x * 8 + (threadIdx.x >> 5);
    if (ch >= NCH) return;
    int lane = threadIdx.x & 31;
    float s = 0.f, ss = 0.f;
    for (int e = lane; e < B_ * S_; e += 32) {
        int b = e / S_, si = e % S_;
        float v = x[(b * NCH + ch) * S_ + si];
        s += v; ss += v * v;
    }
    #pragma unroll
    for (int off = 16; off; off >>= 1) {
        s  += __shfl_xor_sync(0xffffffffu, s,  off);
        ss += __shfl_xor_sync(0xffffffffu, ss, off);
    }
    if (lane == 0) {
        const float inv_n = 1.f / (float)(B_ * S_);
        float mean = s * inv_n;
        float var  = ss * inv_n - mean * mean;
        float a = gamma[ch] * rsqrtf(var + EPSV);
        g_bn_a[ch] = a;
        g_bn_b[ch] = beta[ch] - mean * a;
    }
}

// ---------------- kernel 2: precompute M, v, transposed weights ---------------
__global__ void setup_kernel(const float* __restrict__ w1,
                             const float* __restrict__ w2,
                             const float* __restrict__ ws1,
                             const float* __restrict__ bs1,
                             const float* __restrict__ ws2) {
    int idx = blockIdx.x * blockDim.x + threadIdx.x;
    if (idx < 4096) {
        int b = idx >> 6, a = idx & 63;
        float acc = 0.f;
        #pragma unroll 4
        for (int s = 0; s < 128; ++s)
            acc += ws1[s * 64 + a] * ws2[s * 64 + b];
        g_Mt[b * 64 + a] = acc;
        g_w2t[idx] = w2[(idx & 63) * 64 + (idx >> 6)];
    }
    if (idx < C_ * 64) g_w1t[idx] = w1[(idx & 63) * C_ + (idx >> 6)];
    if (idx < 64) {
        float acc = 0.f;
        #pragma unroll 4
        for (int s = 0; s < 128; ++s)
            acc += ws2[s * 64 + idx] * bs1[s];
        g_v[idx] = acc;
    }
}

// ---------------- smem layout (float offsets) ----------------------------------
#define OFF_W1T   0        // 256
#define OFF_B1    256      // 64
#define OFF_B2    320      // 64
#define OFF_V     384      // 64
#define OFF_W2T   448      // 4096
#define OFF_MT    4544     // 4096 (aliased later: LT + vh)
#define OFF_WW    8640     // 4096
#define OFF_PT    12736    // 4864 (aliased earlier: XN)
#define OFF_H1G   17600    // 64*85 = 5440 (h1, later G)
#define OFF_H     23040    // 64*85 = 5440
#define SMEM_FLOATS 28480
#define SMEM_BYTES (SMEM_FLOATS * 4)   // 113,920 B -> 2 blocks/SM
// aliases:
#define OFF_XN    OFF_PT          // 4*85 = 340 (dead before PT written)
#define OFF_LT    OFF_MT          // 4*20*20 = 1600 (Mt dead after D+E)
#define OFF_VH    (OFF_MT + 1600) // 4*20

__global__ __launch_bounds__(256, 2)
void geo_gcn_main_kernel(const float* __restrict__ x,
                         const float* __restrict__ b1g,
                         const float* __restrict__ b2g,
                         const float* __restrict__ Wg,
                         float* __restrict__ out) {
    extern __shared__ float sm[];
    const int tid = threadIdx.x;

    // ---- cooperative weight load (float4, all L2-resident) ----
    #pragma unroll
    for (int i = 0; i < 4; ++i) {
        int p = (i * 256 + tid) * 4;
        *(float4*)&sm[OFF_W2T + p] = *(const float4*)&g_w2t[p];
        *(float4*)&sm[OFF_MT  + p] = *(const float4*)&g_Mt[p];
        *(float4*)&sm[OFF_WW  + p] = *(const float4*)&Wg[p];
    }
    sm[OFF_W1T + tid] = g_w1t[tid];
    if (tid < 64) {
        sm[OFF_B1 + tid] = b1g[tid];
        sm[OFF_B2 + tid] = b2g[tid];
        sm[OFF_V  + tid] = g_v[tid];
    }

    const int pix0 = blockIdx.x * PPB;

    // ---- Phase A: load + BN the 4 pixels' (4 x 19) slices, pad cols -> 0 ----
    for (int idx = tid; idx < C_ * AST; idx += 256) {
        int c = idx / AST, col = idx % AST;
        float v = 0.f;
        if (col < NC) {
            int p = col / 20, j = col % 20;
            if (j < J_) {
                int pix = pix0 + p;
                int s  = pix % S_;
                int tt = (pix / S_) & (T_ - 1);
                int bb = pix / (S_ * T_);
                int ch = (c * J_ + j) * T_ + tt;
                v = x[(bb * NCH + ch) * S_ + s] * g_bn_a[ch] + g_bn_b[ch];
            }
        }
        sm[OFF_XN + idx] = v;
    }
    __syncthreads();

    const int dg = tid & 15, cg = tid >> 4;
    const int d0 = dg * 4, col0 = cg * 5;
    const int mypix = cg >> 2;
    const int jloc0 = (cg & 3) * 5;

    // ---- Phase B: h1 = relu(W1 xn + b1) ----
    {
        u64 acc[2][5];
        {
            float4 bb = *(const float4*)&sm[OFF_B1 + d0];
            u64 blo = pk2(bb.x, bb.y), bhi = pk2(bb.z, bb.w);
            #pragma unroll
            for (int r = 0; r < 5; ++r) { acc[0][r] = blo; acc[1][r] = bhi; }
        }
        #pragma unroll
        for (int k = 0; k < C_; ++k) {
            u64 wl, wh;
            lds_v2u64(&sm[OFF_W1T + k * 64 + d0], wl, wh);
            #pragma unroll
            for (int r = 0; r < 5; ++r) {
                u64 a2 = dup2(sm[OFF_XN + k * AST + col0 + r]);
                fma2(acc[0][r], wl, a2);
                fma2(acc[1][r], wh, a2);
            }
        }
        #pragma unroll
        for (int i = 0; i < 2; ++i)
            #pragma unroll
            for (int r = 0; r < 5; ++r) {
                float lo, hi; upk2(acc[i][r], lo, hi);
                sm[OFF_H1G + (d0 + 2 * i)     * AST + col0 + r] = fmaxf(lo, 0.f);
                sm[OFF_H1G + (d0 + 2 * i + 1) * AST + col0 + r] = fmaxf(hi, 0.f);
            }
    }
    __syncthreads();

    // ---- Phase C: H = relu(W2 h1 + b2) ----
    {
        u64 acc[2][5];
        {
            float4 bb = *(const float4*)&sm[OFF_B2 + d0];
            u64 blo = pk2(bb.x, bb.y), bhi = pk2(bb.z, bb.w);
            #pragma unroll
            for (int r = 0; r < 5; ++r) { acc[0][r] = blo; acc[1][r] = bhi; }
        }
        #pragma unroll 8
        for (int k = 0; k < 64; ++k) {
            u64 wl, wh;
            lds_v2u64(&sm[OFF_W2T + k * 64 + d0], wl, wh);
            #pragma unroll
            for (int r = 0; r < 5; ++r) {
                u64 a2 = dup2(sm[OFF_H1G + k * AST + col0 + r]);
                fma2(acc[0][r], wl, a2);
                fma2(acc[1][r], wh, a2);
            }
        }
        #pragma unroll
        for (int i = 0; i < 2; ++i)
            #pragma unroll
            for (int r = 0; r < 5; ++r) {
                float lo, hi; upk2(acc[i][r], lo, hi);
                sm[OFF_H + (d0 + 2 * i)     * AST + col0 + r] = fmaxf(lo, 0.f);
                sm[OFF_H + (d0 + 2 * i + 1) * AST + col0 + r] = fmaxf(hi, 0.f);
            }
    }
    __syncthreads();

    // ---- Phase D+E fused: G = M H (into h1 buffer), Pt[j][o] = W^T H ----
    {
        u64 accG[2][5], accP[2][5];
        #pragma unroll
        for (int i = 0; i < 2; ++i)
            #pragma unroll
            for (int r = 0; r < 5; ++r) { accG[i][r] = 0ull; accP[i][r] = 0ull; }
        #pragma unroll 4
        for (int k = 0; k < 64; ++k) {
            u64 ml, mh, wl, wh;
            lds_v2u64(&sm[OFF_MT + k * 64 + d0], ml, mh);
            lds_v2u64(&sm[OFF_WW + k * 64 + d0], wl, wh);
            #pragma unroll
            for (int r = 0; r < 5; ++r) {
                u64 a2 = dup2(sm[OFF_H + k * AST + col0 + r]);
                fma2(accG[0][r], ml, a2);
                fma2(accG[1][r], mh, a2);
                fma2(accP[0][r], wl, a2);
                fma2(accP[1][r], wh, a2);
            }
        }
        #pragma unroll
        for (int i = 0; i < 2; ++i)
            #pragma unroll
            for (int r = 0; r < 5; ++r) {
                float lo, hi; upk2(accG[i][r], lo, hi);
                sm[OFF_H1G + (d0 + 2 * i)     * AST + col0 + r] = lo;
                sm[OFF_H1G + (d0 + 2 * i + 1) * AST + col0 + r] = hi;
            }
        #pragma unroll
        for (int r = 0; r < 5; ++r) {
            int j = jloc0 + r;
            if (j < J_) {
                float g0, g1, g2, g3;
                upk2(accP[0][r], g0, g1);
                upk2(accP[1][r], g2, g3);
                *(float4*)&sm[OFF_PT + (mypix * J_ + j) * 64 + d0] =
                    make_float4(g0, g1, g2, g3);
            }
        }
    }
    __syncthreads();

    // ---- Phase F: logits LT[p][k][j] = sum_a H[a][j] G[a][k]; vh[p][k] ----
    if (tid < 200) {
        int p  = tid / 50;
        int q  = tid % 50;
        int j0 = (q / 5) * 2;
        int k0 = (q % 5) * 4;
        int hb = OFF_H   + p * 20;
        int gb = OFF_H1G + p * 20;
        float acc[2][4];
        #pragma unroll
        for (int r = 0; r < 2; ++r)
            #pragma unroll
            for (int i = 0; i < 4; ++i) acc[r][i] = 0.f;
        #pragma unroll 8
        for (int a = 0; a < 64; ++a) {
            float h0 = sm[hb + a * AST + j0];
            float h1 = sm[hb + a * AST + j0 + 1];
            float g[4];
            #pragma unroll
            for (int i = 0; i < 4; ++i) g[i] = sm[gb + a * AST + k0 + i];
            #pragma unroll
            for (int i = 0; i < 4; ++i) { acc[0][i] += h0 * g[i]; acc[1][i] += h1 * g[i]; }
        }
        #pragma unroll
        for (int i = 0; i < 4; ++i)
            #pragma unroll
            for (int r = 0; r < 2; ++r)
                sm[OFF_LT + (p * 20 + k0 + i) * 20 + (j0 + r)] = acc[r][i];
    } else {
        int idx = tid - 200;
        #pragma unroll
        for (int it = 0; it < 2; ++it, idx += 56) {
            if (idx < 80) {
                int p = idx / 20, k = idx % 20;
                float acc = 0.f;
                #pragma unroll 8
                for (int b = 0; b < 64; ++b)
                    acc += sm[OFF_V + b] * sm[OFF_H + b * AST + p * 20 + k];
                sm[OFF_VH + idx] = acc;
            }
        }
    }
    __syncthreads();

    // ---- softmax over k, per (pixel, j) ----
    if (tid < PPB * J_) {
        int p = tid / J_, j = tid % J_;
        float l[J_];
        float mx = -1e30f;
        #pragma unroll
        for (int k = 0; k < J_; ++k) {
            l[k] = sm[OFF_LT + (p * 20 + k) * 20 + j] + sm[OFF_VH + p * 20 + k];
            mx = fmaxf(mx, l[k]);
        }
        float sum = 0.f;
        #pragma unroll
        for (int k = 0; k < J_; ++k) { l[k] = __expf(l[k] - mx); sum += l[k]; }
        float inv = 1.f / sum;
        #pragma unroll
        for (int k = 0; k < J_; ++k)
            sm[OFF_LT + (p * 20 + k) * 20 + j] = l[k] * inv;
    }
    __syncthreads();

    // ---- Final: out[o][j] = sum_k att[j][k] * Pt[k][o] ----
    {
        u64 acc[2][5];
        #pragma unroll
        for (int i = 0; i < 2; ++i)
            #pragma unroll
            for (int r = 0; r < 5; ++r) acc[i][r] = 0ull;
        #pragma unroll 4
        for (int k = 0; k < J_; ++k) {
            u64 pl, ph;
            lds_v2u64(&sm[OFF_PT + (mypix * J_ + k) * 64 + d0], pl, ph);
            #pragma unroll
            for (int r = 0; r < 5; ++r) {
                u64 a2 = dup2(sm[OFF_LT + (mypix * 20 + k) * 20 + jloc0 + r]);
                fma2(acc[0][r], pl, a2);
                fma2(acc[1][r], ph, a2);
            }
        }
        int pix = pix0 + mypix;
        int s  = pix % S_;
        int tt = (pix / S_) & (T_ - 1);
        int bb = pix / (S_ * T_);
        int base = ((bb * 64) * J_) * (T_ * S_) + tt * S_ + s;
        #pragma unroll
        for (int r = 0; r < 5; ++r) {
            int j = jloc0 + r;
            if (j < J_) {
                float v0, v1, v2, v3;
                upk2(acc[0][r], v0, v1);
                upk2(acc[1][r], v2, v3);
                out[base + ((d0 + 0) * J_ + j) * (T_ * S_)] = v0;
                out[base + ((d0 + 1) * J_ + j) * (T_ * S_)] = v1;
                out[base + ((d0 + 2) * J_ + j) * (T_ * S_)] = v2;
                out[base + ((d0 + 3) * J_ + j) * (T_ * S_)] = v3;
            }
        }
    }
}

// ------------------------------ launcher --------------------------------------
extern "C" void kernel_launch(void* const* d_in, const int* in_sizes, int n_in,
                              void* d_out, int out_size) {
    const float* x     = (const float*)d_in[0];
    const float* gamma = (const float*)d_in[1];
    const float* beta  = (const float*)d_in[2];
    const float* w1    = (const float*)d_in[3];
    const float* b1    = (const float*)d_in[4];
    const float* w2    = (const float*)d_in[5];
    const float* b2    = (const float*)d_in[6];
    const float* ws1   = (const float*)d_in[7];
    const float* bs1   = (const float*)d_in[8];
    const float* ws2   = (const float*)d_in[9];
    // d_in[10] = bs2 (softmax-invariant), d_in[11] = W
    const float* W     = (const float*)d_in[11];
    float* out = (float*)d_out;

    cudaFuncSetAttribute(geo_gcn_main_kernel,
                         cudaFuncAttributeMaxDynamicSharedMemorySize, SMEM_BYTES);

    bn_stats_kernel<<<NCH / 8, 256>>>(x, gamma, beta);
    setup_kernel<<<16, 256>>>(w1, w2, ws1, bs1, ws2);
    geo_gcn_main_kernel<<<NPIX / PPB, 256, SMEM_BYTES>>>(x, b1, b2, W, out);
}

// round 4
// speedup vs baseline: 2.2555x; 1.0289x over previous
#include <cuda_runtime.h>
#include <cuda_bf16.h>
#include <math.h>

// Problem constants
#define B_  16
#define C_  4
#define J_  19
#define T_  256
#define S_  10
#define NCH (C_*J_*T_)          // 19456 BN channels
#define NPIX (B_*T_*S_)         // 40960 pixels
#define EPSV 1e-5f

#define PPB 4                   // pixels per block
#define NC  80                  // data columns per block
#define AST 84                  // activation row stride (mult of 4 for LDS.128)
#define NTH 320                 // 16 d-groups x 20 col-groups

typedef unsigned long long u64;

// ---- f32x2 packed-math helpers ------------------------------------------------
__device__ __forceinline__ u64 dup2(float a) {
    u64 r; asm("mov.b64 %0, {%1, %1};" : "=l"(r) : "f"(a)); return r;
}
__device__ __forceinline__ void upk2(u64 v, float& lo, float& hi) {
    asm("mov.b64 {%0, %1}, %2;" : "=f"(lo), "=f"(hi) : "l"(v));
}
__device__ __forceinline__ void fma2(u64& d, u64 a, u64 b) {
    asm("fma.rn.f32x2 %0, %1, %2, %0;" : "+l"(d) : "l"(a), "l"(b));
}
// 16B shared load -> two packed f32x2 (i.e. 4 consecutive floats)
__device__ __forceinline__ void lds_v2u64(const float* p, u64& lo, u64& hi) {
    unsigned a = (unsigned)__cvta_generic_to_shared(p);
    asm("ld.shared.v2.u64 {%0, %1}, [%2];" : "=l"(lo), "=l"(hi) : "r"(a));
}

// ---------------- device scratch ----------------------------------------------
__device__ float g_bn_a[NCH];
__device__ float g_bn_b[NCH];
__device__ float g_w1t[C_*64];      // w1t[c][d]
__device__ float g_w2t[64*64];      // w2t[k][d]
__device__ float g_Mt[64*64];       // Mt[b][a] = M[a][b]
__device__ float g_v[64];           // v[b] = sum_s ws2[s][b]*bs1[s]

// ---------------- kernel 1: BN statistics -> per-channel affine ---------------
__global__ void bn_stats_kernel(const float* __restrict__ x,
                                const float* __restrict__ gamma,
                                const float* __restrict__ beta) {
    int ch = blockIdx.x * 8 + (threadIdx.x >> 5);
    if (ch >= NCH) return;
    int lane = threadIdx.x & 31;
    float s = 0.f, ss = 0.f;
    for (int e = lane; e < B_ * S_; e += 32) {
        int b = e / S_, si = e % S_;
        float v = x[(b * NCH + ch) * S_ + si];
        s += v; ss += v * v;
    }
    #pragma unroll
    for (int off = 16; off; off >>= 1) {
        s  += __shfl_xor_sync(0xffffffffu, s,  off);
        ss += __shfl_xor_sync(0xffffffffu, ss, off);
    }
    if (lane == 0) {
        const float inv_n = 1.f / (float)(B_ * S_);
        float mean = s * inv_n;
        float var  = ss * inv_n - mean * mean;
        float a = gamma[ch] * rsqrtf(var + EPSV);
        g_bn_a[ch] = a;
        g_bn_b[ch] = beta[ch] - mean * a;
    }
}

// ---------------- kernel 2: precompute M, v, transposed weights ---------------
__global__ void setup_kernel(const float* __restrict__ w1,
                             const float* __restrict__ w2,
                             const float* __restrict__ ws1,
                             const float* __restrict__ bs1,
                             const float* __restrict__ ws2) {
    int idx = blockIdx.x * blockDim.x + threadIdx.x;
    if (idx < 4096) {
        int b = idx >> 6, a = idx & 63;
        float acc = 0.f;
        #pragma unroll 4
        for (int s = 0; s < 128; ++s)
            acc += ws1[s * 64 + a] * ws2[s * 64 + b];
        g_Mt[b * 64 + a] = acc;
        g_w2t[idx] = w2[(idx & 63) * 64 + (idx >> 6)];
    }
    if (idx < C_ * 64) g_w1t[idx] = w1[(idx & 63) * C_ + (idx >> 6)];
    if (idx < 64) {
        float acc = 0.f;
        #pragma unroll 4
        for (int s = 0; s < 128; ++s)
            acc += ws2[s * 64 + idx] * bs1[s];
        g_v[idx] = acc;
    }
}

// ---------------- smem layout (float offsets) ----------------------------------
#define OFF_W1T   0        // 256
#define OFF_B1    256      // 64
#define OFF_B2    320      // 64
#define OFF_V     384      // 64
#define OFF_W2T   448      // 4096
#define OFF_MT    4544     // 4096 (aliased later: LT + vh)
#define OFF_WW    8640     // 4096
#define OFF_PT    12736    // 4864 (aliased earlier: XN)
#define OFF_H1G   17600    // 64*84 = 5376 (h1, later G)
#define OFF_H     22976    // 64*84 = 5376
#define SMEM_FLOATS 28352
#define SMEM_BYTES (SMEM_FLOATS * 4)   // 113,408 B -> 2 blocks/SM
// aliases:
#define OFF_XN    OFF_PT          // 4*84 = 336 (dead before PT written)
#define OFF_LT    OFF_MT          // 4*20*20 = 1600 (Mt dead after D+E)
#define OFF_VH    (OFF_MT + 1600) // 4*20

__global__ __launch_bounds__(NTH, 2)
void geo_gcn_main_kernel(const float* __restrict__ x,
                         const float* __restrict__ b1g,
                         const float* __restrict__ b2g,
                         const float* __restrict__ Wg,
                         float* __restrict__ out) {
    extern __shared__ float sm[];
    const int tid = threadIdx.x;

    // ---- cooperative weight load (float4, all L2-resident) ----
    #pragma unroll
    for (int i = 0; i < 4; ++i) {
        int q = i * NTH + tid;
        if (q < 1024) {
            int p = q * 4;
            *(float4*)&sm[OFF_W2T + p] = *(const float4*)&g_w2t[p];
            *(float4*)&sm[OFF_MT  + p] = *(const float4*)&g_Mt[p];
            *(float4*)&sm[OFF_WW  + p] = *(const float4*)&Wg[p];
        }
    }
    if (tid < 256) sm[OFF_W1T + tid] = g_w1t[tid];
    if (tid < 64) {
        sm[OFF_B1 + tid] = b1g[tid];
        sm[OFF_B2 + tid] = b2g[tid];
        sm[OFF_V  + tid] = g_v[tid];
    }

    const int pix0 = blockIdx.x * PPB;

    // ---- Phase A: load + BN the 4 pixels' (4 x 19) slices, pad cols -> 0 ----
    for (int idx = tid; idx < C_ * AST; idx += NTH) {
        int c = idx / AST, col = idx % AST;
        float v = 0.f;
        if (col < NC) {
            int p = col / 20, j = col % 20;
            if (j < J_) {
                int pix = pix0 + p;
                int s  = pix % S_;
                int tt = (pix / S_) & (T_ - 1);
                int bb = pix / (S_ * T_);
                int ch = (c * J_ + j) * T_ + tt;
                v = x[(bb * NCH + ch) * S_ + s] * g_bn_a[ch] + g_bn_b[ch];
            }
        }
        sm[OFF_XN + idx] = v;
    }
    __syncthreads();

    const int dg = tid & 15, cg = tid >> 4;       // cg: 0..19
    const int d0 = dg * 4, col0 = cg * 4;
    const int mypix = cg / 5;
    const int jloc0 = (cg % 5) * 4;               // local j of first column

    // ---- Phase B: h1 = relu(W1 xn + b1) ----
    {
        u64 acc[4][2];
        {
            float4 bb = *(const float4*)&sm[OFF_B1 + d0];
            #pragma unroll
            for (int i = 0; i < 4; ++i) { u64 b2v = dup2((&bb.x)[i]); acc[i][0] = b2v; acc[i][1] = b2v; }
        }
        #pragma unroll
        for (int k = 0; k < C_; ++k) {
            float4 w = *(const float4*)&sm[OFF_W1T + k * 64 + d0];
            u64 a01, a23;
            lds_v2u64(&sm[OFF_XN + k * AST + col0], a01, a23);
            #pragma unroll
            for (int i = 0; i < 4; ++i) {
                u64 wd = dup2((&w.x)[i]);
                fma2(acc[i][0], wd, a01);
                fma2(acc[i][1], wd, a23);
            }
        }
        #pragma unroll
        for (int i = 0; i < 4; ++i) {
            float v0, v1, v2, v3;
            upk2(acc[i][0], v0, v1); upk2(acc[i][1], v2, v3);
            *(float4*)&sm[OFF_H1G + (d0 + i) * AST + col0] =
                make_float4(fmaxf(v0,0.f), fmaxf(v1,0.f), fmaxf(v2,0.f), fmaxf(v3,0.f));
        }
    }
    __syncthreads();

    // ---- Phase C: H = relu(W2 h1 + b2) ----
    {
        u64 acc[4][2];
        {
            float4 bb = *(const float4*)&sm[OFF_B2 + d0];
            #pragma unroll
            for (int i = 0; i < 4; ++i) { u64 b2v = dup2((&bb.x)[i]); acc[i][0] = b2v; acc[i][1] = b2v; }
        }
        #pragma unroll 8
        for (int k = 0; k < 64; ++k) {
            float4 w = *(const float4*)&sm[OFF_W2T + k * 64 + d0];
            u64 a01, a23;
            lds_v2u64(&sm[OFF_H1G + k * AST + col0], a01, a23);
            #pragma unroll
            for (int i = 0; i < 4; ++i) {
                u64 wd = dup2((&w.x)[i]);
                fma2(acc[i][0], wd, a01);
                fma2(acc[i][1], wd, a23);
            }
        }
        #pragma unroll
        for (int i = 0; i < 4; ++i) {
            float v0, v1, v2, v3;
            upk2(acc[i][0], v0, v1); upk2(acc[i][1], v2, v3);
            *(float4*)&sm[OFF_H + (d0 + i) * AST + col0] =
                make_float4(fmaxf(v0,0.f), fmaxf(v1,0.f), fmaxf(v2,0.f), fmaxf(v3,0.f));
        }
    }
    __syncthreads();

    // ---- Phase D+E fused: G = M H (into h1 buffer), Pt[j][o] = W^T H ----
    {
        u64 accG[4][2], accP[4][2];
        #pragma unroll
        for (int i = 0; i < 4; ++i) {
            accG[i][0] = 0ull; accG[i][1] = 0ull;
            accP[i][0] = 0ull; accP[i][1] = 0ull;
        }
        #pragma unroll 4
        for (int k = 0; k < 64; ++k) {
            float4 wm = *(const float4*)&sm[OFF_MT + k * 64 + d0];
            float4 ww = *(const float4*)&sm[OFF_WW + k * 64 + d0];
            u64 a01, a23;
            lds_v2u64(&sm[OFF_H + k * AST + col0], a01, a23);
            #pragma unroll
            for (int i = 0; i < 4; ++i) {
                u64 md = dup2((&wm.x)[i]);
                u64 wd = dup2((&ww.x)[i]);
                fma2(accG[i][0], md, a01);
                fma2(accG[i][1], md, a23);
                fma2(accP[i][0], wd, a01);
                fma2(accP[i][1], wd, a23);
            }
        }
        #pragma unroll
        for (int i = 0; i < 4; ++i) {
            float v0, v1, v2, v3;
            upk2(accG[i][0], v0, v1); upk2(accG[i][1], v2, v3);
            *(float4*)&sm[OFF_H1G + (d0 + i) * AST + col0] = make_float4(v0, v1, v2, v3);
        }
        #pragma unroll
        for (int r = 0; r < 4; ++r) {
            int j = jloc0 + r;
            if (j < J_) {
                float p0, p1, p2, p3, dum;
                if (r & 1) { upk2(accP[0][r >> 1], dum, p0); upk2(accP[1][r >> 1], dum, p1);
                             upk2(accP[2][r >> 1], dum, p2); upk2(accP[3][r >> 1], dum, p3); }
                else       { upk2(accP[0][r >> 1], p0, dum); upk2(accP[1][r >> 1], p1, dum);
                             upk2(accP[2][r >> 1], p2, dum); upk2(accP[3][r >> 1], p3, dum); }
                *(float4*)&sm[OFF_PT + (mypix * J_ + j) * 64 + d0] =
                    make_float4(p0, p1, p2, p3);
            }
        }
    }
    __syncthreads();

    // ---- Phase F: logits LT[p][k][j] = sum_a H[a][j] G[a][k]; vh[p][k] ----
    if (tid < 200) {
        int p  = tid / 50;
        int q  = tid % 50;
        int j0 = (q / 5) * 2;
        int k0 = (q % 5) * 4;
        int hb = OFF_H   + p * 20;
        int gb = OFF_H1G + p * 20;
        u64 acc[2][2];   // [j-pair element][k-pair]
        acc[0][0] = acc[0][1] = acc[1][0] = acc[1][1] = 0ull;
        #pragma unroll 8
        for (int a = 0; a < 64; ++a) {
            u64 h0 = dup2(sm[hb + a * AST + j0]);
            u64 h1 = dup2(sm[hb + a * AST + j0 + 1]);
            u64 g01, g23;
            lds_v2u64(&sm[gb + a * AST + k0], g01, g23);
            fma2(acc[0][0], h0, g01); fma2(acc[0][1], h0, g23);
            fma2(acc[1][0], h1, g01); fma2(acc[1][1], h1, g23);
        }
        #pragma unroll
        for (int r = 0; r < 2; ++r) {
            float l0, l1, l2, l3;
            upk2(acc[r][0], l0, l1); upk2(acc[r][1], l2, l3);
            sm[OFF_LT + (p * 20 + k0 + 0) * 20 + (j0 + r)] = l0;
            sm[OFF_LT + (p * 20 + k0 + 1) * 20 + (j0 + r)] = l1;
            sm[OFF_LT + (p * 20 + k0 + 2) * 20 + (j0 + r)] = l2;
            sm[OFF_LT + (p * 20 + k0 + 3) * 20 + (j0 + r)] = l3;
        }
    } else if (tid < 280) {
        int idx = tid - 200;                 // 0..79 -> (pixel, k)
        int p = idx / 20, k = idx % 20;
        float acc = 0.f;
        #pragma unroll 8
        for (int b = 0; b < 64; ++b)
            acc += sm[OFF_V + b] * sm[OFF_H + b * AST + p * 20 + k];
        sm[OFF_VH + idx] = acc;
    }
    __syncthreads();

    // ---- softmax over k, per (pixel, j) ----
    if (tid < PPB * J_) {
        int p = tid / J_, j = tid % J_;
        float l[J_];
        float mx = -1e30f;
        #pragma unroll
        for (int k = 0; k < J_; ++k) {
            l[k] = sm[OFF_LT + (p * 20 + k) * 20 + j] + sm[OFF_VH + p * 20 + k];
            mx = fmaxf(mx, l[k]);
        }
        float sum = 0.f;
        #pragma unroll
        for (int k = 0; k < J_; ++k) { l[k] = __expf(l[k] - mx); sum += l[k]; }
        float inv = 1.f / sum;
        #pragma unroll
        for (int k = 0; k < J_; ++k)
            sm[OFF_LT + (p * 20 + k) * 20 + j] = l[k] * inv;
    }
    __syncthreads();

    // ---- Final: out[o][j] = sum_k att[j][k] * Pt[k][o] ----
    {
        u64 acc[4][2];
        #pragma unroll
        for (int i = 0; i < 4; ++i) { acc[i][0] = 0ull; acc[i][1] = 0ull; }
        #pragma unroll
        for (int k = 0; k < J_; ++k) {
            float4 pt = *(const float4*)&sm[OFF_PT + (mypix * J_ + k) * 64 + d0];
            u64 a01, a23;
            lds_v2u64(&sm[OFF_LT + (mypix * 20 + k) * 20 + jloc0], a01, a23);
            #pragma unroll
            for (int i = 0; i < 4; ++i) {
                u64 pd = dup2((&pt.x)[i]);
                fma2(acc[i][0], pd, a01);
                fma2(acc[i][1], pd, a23);
            }
        }
        int pix = pix0 + mypix;
        int s  = pix % S_;
        int tt = (pix / S_) & (T_ - 1);
        int bb = pix / (S_ * T_);
        int base = ((bb * 64) * J_) * (T_ * S_) + tt * S_ + s;
        #pragma unroll
        for (int i = 0; i < 4; ++i) {
            float v0, v1, v2, v3;
            upk2(acc[i][0], v0, v1); upk2(acc[i][1], v2, v3);
            int ob = base + (d0 + i) * J_ * (T_ * S_);
            int j = jloc0;
            out[ob + j * (T_ * S_)] = v0;
            if (j + 1 < J_) out[ob + (j + 1) * (T_ * S_)] = v1;
            if (j + 2 < J_) out[ob + (j + 2) * (T_ * S_)] = v2;
            if (j + 3 < J_) out[ob + (j + 3) * (T_ * S_)] = v3;
        }
    }
}

// ------------------------------ launcher --------------------------------------
extern "C" void kernel_launch(void* const* d_in, const int* in_sizes, int n_in,
                              void* d_out, int out_size) {
    const float* x     = (const float*)d_in[0];
    const float* gamma = (const float*)d_in[1];
    const float* beta  = (const float*)d_in[2];
    const float* w1    = (const float*)d_in[3];
    const float* b1    = (const float*)d_in[4];
    const float* w2    = (const float*)d_in[5];
    const float* b2    = (const float*)d_in[6];
    const float* ws1   = (const float*)d_in[7];
    const float* bs1   = (const float*)d_in[8];
    const float* ws2   = (const float*)d_in[9];
    // d_in[10] = bs2 (softmax-invariant), d_in[11] = W
    const float* W     = (const float*)d_in[11];
    float* out = (float*)d_out;

    cudaFuncSetAttribute(geo_gcn_main_kernel,
                         cudaFuncAttributeMaxDynamicSharedMemorySize, SMEM_BYTES);

    bn_stats_kernel<<<NCH / 8, 256>>>(x, gamma, beta);
    setup_kernel<<<16, 256>>>(w1, w2, ws1, bs1, ws2);
    geo_gcn_main_kernel<<<NPIX / PPB, NTH, SMEM_BYTES>>>(x, b1, b2, W, out);
}

// round 5
// speedup vs baseline: 2.4647x; 1.0927x over previous
#include <cuda_runtime.h>
#include <cuda_bf16.h>
#include <math.h>

// Problem constants
#define B_  16
#define C_  4
#define J_  19
#define T_  256
#define S_  10
#define NCH (C_*J_*T_)          // 19456 BN channels
#define NPIX (B_*T_*S_)         // 40960 pixels
#define EPSV 1e-5f

#define PPB 4                   // pixels per block
#define NC  80                  // data columns per block (4 pix x 20)
#define AST 84                  // activation row stride
#define NTH 320                 // 16 d-groups x 20 col-groups

typedef unsigned long long u64;

// ---- f32x2 packed-math helpers ------------------------------------------------
__device__ __forceinline__ u64 dup2(float a) {
    u64 r; asm("mov.b64 %0, {%1, %1};" : "=l"(r) : "f"(a)); return r;
}
__device__ __forceinline__ void upk2(u64 v, float& lo, float& hi) {
    asm("mov.b64 {%0, %1}, %2;" : "=f"(lo), "=f"(hi) : "l"(v));
}
__device__ __forceinline__ void fma2(u64& d, u64 a, u64 b) {
    asm("fma.rn.f32x2 %0, %1, %2, %0;" : "+l"(d) : "l"(a), "l"(b));
}
__device__ __forceinline__ void lds_v2u64(const float* p, u64& lo, u64& hi) {
    unsigned a = (unsigned)__cvta_generic_to_shared(p);
    asm("ld.shared.v2.u64 {%0, %1}, [%2];" : "=l"(lo), "=l"(hi) : "r"(a));
}

// ---------------- device scratch ----------------------------------------------
__device__ float g_bn_a[NCH];
__device__ float g_bn_b[NCH];
__device__ float g_w1t[C_*64];
__device__ float g_w2t[64*64];
__device__ float g_Mt[64*64];
__device__ float g_v[64];
__device__ float g_xn[(size_t)NPIX * 76];   // normalized input, pixel-major

// ---------------- kernel 1: BN statistics -> per-channel affine ---------------
__global__ void bn_stats_kernel(const float* __restrict__ x,
                                const float* __restrict__ gamma,
                                const float* __restrict__ beta) {
    int ch = blockIdx.x * 8 + (threadIdx.x >> 5);
    if (ch >= NCH) return;
    int lane = threadIdx.x & 31;
    float s = 0.f, ss = 0.f;
    for (int e = lane; e < B_ * S_; e += 32) {
        int b = e / S_, si = e % S_;
        float v = x[(b * NCH + ch) * S_ + si];
        s += v; ss += v * v;
    }
    #pragma unroll
    for (int off = 16; off; off >>= 1) {
        s  += __shfl_xor_sync(0xffffffffu, s,  off);
        ss += __shfl_xor_sync(0xffffffffu, ss, off);
    }
    if (lane == 0) {
        const float inv_n = 1.f / (float)(B_ * S_);
        float mean = s * inv_n;
        float var  = ss * inv_n - mean * mean;
        float a = gamma[ch] * rsqrtf(var + EPSV);
        g_bn_a[ch] = a;
        g_bn_b[ch] = beta[ch] - mean * a;
    }
}

// ---------------- kernel 2: precompute M, v, transposed weights ---------------
__global__ void setup_kernel(const float* __restrict__ w1,
                             const float* __restrict__ w2,
                             const float* __restrict__ ws1,
                             const float* __restrict__ bs1,
                             const float* __restrict__ ws2) {
    int idx = blockIdx.x * blockDim.x + threadIdx.x;
    if (idx < 4096) {
        int b = idx >> 6, a = idx & 63;
        float acc = 0.f;
        #pragma unroll 4
        for (int s = 0; s < 128; ++s)
            acc += ws1[s * 64 + a] * ws2[s * 64 + b];
        g_Mt[b * 64 + a] = acc;
        g_w2t[idx] = w2[(idx & 63) * 64 + (idx >> 6)];
    }
    if (idx < C_ * 64) g_w1t[idx] = w1[(idx & 63) * C_ + (idx >> 6)];
    if (idx < 64) {
        float acc = 0.f;
        #pragma unroll 4
        for (int s = 0; s < 128; ++s)
            acc += ws2[s * 64 + idx] * bs1[s];
        g_v[idx] = acc;
    }
}

// ---------------- kernel 3: BN-apply + transpose to pixel-major ----------------
#define XTK 8     // t-steps per block (80 pixels)
__global__ void xn_kernel(const float* __restrict__ x) {
    __shared__ float sa[76 * XTK];
    __shared__ float sb[76 * XTK];
    __shared__ float tile[80 * 80];   // [pixloc][ch]
    int b  = blockIdx.x >> 5;
    int t0 = (blockIdx.x & 31) * XTK;
    int tid = threadIdx.x;            // 256

    for (int u = tid; u < 76 * XTK; u += 256) {
        int ch = u / XTK, tt = u % XTK;
        sa[u] = g_bn_a[ch * 256 + t0 + tt];
        sb[u] = g_bn_b[ch * 256 + t0 + tt];
    }
    __syncthreads();

    for (int u = tid; u < 76 * 20; u += 256) {
        int ch = u / 20, i4 = (u % 20) * 4;
        float4 v = *(const float4*)&x[((size_t)(b * 76 + ch)) * 2560 + t0 * 10 + i4];
        #pragma unroll
        for (int q = 0; q < 4; ++q) {
            int i = i4 + q;
            int tt = i / 10;
            tile[i * 80 + ch] = (&v.x)[q] * sa[ch * XTK + tt] + sb[ch * XTK + tt];
        }
    }
    __syncthreads();

    for (int u = tid; u < 80 * 19; u += 256) {
        int i = u / 19, chq = u % 19;
        float4 v = *(float4*)&tile[i * 80 + chq * 4];
        *(float4*)&g_xn[((size_t)(b * 2560 + t0 * 10 + i)) * 76 + chq * 4] = v;
    }
}

// ---------------- smem layout (float offsets) ----------------------------------
#define OFF_W1T   0        // 256
#define OFF_B1    256      // 64
#define OFF_B2    320      // 64
#define OFF_V     384      // 64
#define OFF_W2T   448      // 4096
#define OFF_MT    4544     // 4096 (aliased later: LT + VH)
#define OFF_WW    8640     // 4096
#define OFF_XN    12736    // 340
#define OFF_A1    13076    // 64*84 = 5376 : h1 -> G -> AGG
#define OFF_A2    18452    // 64*84 = 5376 : H
#define SMEM_FLOATS 23828
#define SMEM_BYTES (SMEM_FLOATS * 4)   // 95,312 B -> 2 blocks/SM
// aliases (Mt dead after phase D):
#define OFF_LT    OFF_MT          // 4*20*20 = 1600, layout [p][j][k]
#define OFF_VH    (OFF_MT + 1600) // 4*20

__global__ __launch_bounds__(NTH, 2)
void geo_gcn_main_kernel(const float* __restrict__ b1g,
                         const float* __restrict__ b2g,
                         const float* __restrict__ Wg,
                         float* __restrict__ out) {
    extern __shared__ float sm[];
    const int tid = threadIdx.x;

    // ---- cooperative weight load ----
    #pragma unroll
    for (int i = 0; i < 4; ++i) {
        int q = i * NTH + tid;
        if (q < 1024) {
            int p = q * 4;
            *(float4*)&sm[OFF_W2T + p] = *(const float4*)&g_w2t[p];
            *(float4*)&sm[OFF_MT  + p] = *(const float4*)&g_Mt[p];
            *(float4*)&sm[OFF_WW  + p] = *(const float4*)&Wg[p];
        }
    }
    if (tid < 256) sm[OFF_W1T + tid] = g_w1t[tid];
    if (tid < 64) {
        sm[OFF_B1 + tid] = b1g[tid];
        sm[OFF_B2 + tid] = b2g[tid];
        sm[OFF_V  + tid] = g_v[tid];
    }

    const int pix0 = blockIdx.x * PPB;

    // ---- Phase A: coalesced load of 4 pixels' normalized input ----
    if (tid < 76) {
        float4 v = *(const float4*)&g_xn[(size_t)pix0 * 76 + tid * 4];
        int p = tid / 19, chq = tid % 19;
        #pragma unroll
        for (int u = 0; u < 4; ++u) {
            int ch = chq * 4 + u;
            int c = ch / 19, j = ch % 19;
            sm[OFF_XN + c * AST + p * 20 + j] = (&v.x)[u];
        }
    } else if (tid < 92) {
        int u = tid - 76;   // zero the j=19 pads
        sm[OFF_XN + (u >> 2) * AST + (u & 3) * 20 + 19] = 0.f;
    }
    __syncthreads();

    const int dg = tid & 15, cg = tid >> 4;      // cg: 0..19
    const int d0 = dg * 4, col0 = cg * 4;

    // ---- Phase B: h1 = relu(W1 xn + b1)  -> A1 ----
    {
        u64 acc[4][2];
        {
            float4 bb = *(const float4*)&sm[OFF_B1 + d0];
            #pragma unroll
            for (int i = 0; i < 4; ++i) { u64 bv = dup2((&bb.x)[i]); acc[i][0] = bv; acc[i][1] = bv; }
        }
        #pragma unroll
        for (int k = 0; k < C_; ++k) {
            float4 w = *(const float4*)&sm[OFF_W1T + k * 64 + d0];
            u64 a01, a23;
            lds_v2u64(&sm[OFF_XN + k * AST + col0], a01, a23);
            #pragma unroll
            for (int i = 0; i < 4; ++i) {
                u64 wd = dup2((&w.x)[i]);
                fma2(acc[i][0], wd, a01);
                fma2(acc[i][1], wd, a23);
            }
        }
        #pragma unroll
        for (int i = 0; i < 4; ++i) {
            float v0, v1, v2, v3;
            upk2(acc[i][0], v0, v1); upk2(acc[i][1], v2, v3);
            *(float4*)&sm[OFF_A1 + (d0 + i) * AST + col0] =
                make_float4(fmaxf(v0,0.f), fmaxf(v1,0.f), fmaxf(v2,0.f), fmaxf(v3,0.f));
        }
    }
    __syncthreads();

    // ---- Phase C: H = relu(W2 h1 + b2)  -> A2 ----
    {
        u64 acc[4][2];
        {
            float4 bb = *(const float4*)&sm[OFF_B2 + d0];
            #pragma unroll
            for (int i = 0; i < 4; ++i) { u64 bv = dup2((&bb.x)[i]); acc[i][0] = bv; acc[i][1] = bv; }
        }
        #pragma unroll 8
        for (int k = 0; k < 64; ++k) {
            float4 w = *(const float4*)&sm[OFF_W2T + k * 64 + d0];
            u64 a01, a23;
            lds_v2u64(&sm[OFF_A1 + k * AST + col0], a01, a23);
            #pragma unroll
            for (int i = 0; i < 4; ++i) {
                u64 wd = dup2((&w.x)[i]);
                fma2(acc[i][0], wd, a01);
                fma2(acc[i][1], wd, a23);
            }
        }
        #pragma unroll
        for (int i = 0; i < 4; ++i) {
            float v0, v1, v2, v3;
            upk2(acc[i][0], v0, v1); upk2(acc[i][1], v2, v3);
            *(float4*)&sm[OFF_A2 + (d0 + i) * AST + col0] =
                make_float4(fmaxf(v0,0.f), fmaxf(v1,0.f), fmaxf(v2,0.f), fmaxf(v3,0.f));
        }
    }
    __syncthreads();

    // ---- Phase D: G = M H  -> A1 ----
    {
        u64 acc[4][2];
        #pragma unroll
        for (int i = 0; i < 4; ++i) { acc[i][0] = 0ull; acc[i][1] = 0ull; }
        #pragma unroll 8
        for (int k = 0; k < 64; ++k) {
            float4 w = *(const float4*)&sm[OFF_MT + k * 64 + d0];
            u64 a01, a23;
            lds_v2u64(&sm[OFF_A2 + k * AST + col0], a01, a23);
            #pragma unroll
            for (int i = 0; i < 4; ++i) {
                u64 wd = dup2((&w.x)[i]);
                fma2(acc[i][0], wd, a01);
                fma2(acc[i][1], wd, a23);
            }
        }
        #pragma unroll
        for (int i = 0; i < 4; ++i) {
            float v0, v1, v2, v3;
            upk2(acc[i][0], v0, v1); upk2(acc[i][1], v2, v3);
            *(float4*)&sm[OFF_A1 + (d0 + i) * AST + col0] = make_float4(v0, v1, v2, v3);
        }
    }
    __syncthreads();

    // ---- Phase F: logits LT[p][j][k] = sum_a H[a][j] G[a][k]; vh[p][k] ----
    if (tid < 200) {
        int p  = tid / 50;
        int q  = tid % 50;
        int j0 = (q / 5) * 2;     // 0..18
        int k0 = (q % 5) * 4;     // 0..16
        int hb = OFF_A2 + p * 20;
        int gb = OFF_A1 + p * 20;
        u64 acc[2][2];
        acc[0][0] = acc[0][1] = acc[1][0] = acc[1][1] = 0ull;
        #pragma unroll 8
        for (int a = 0; a < 64; ++a) {
            u64 h0 = dup2(sm[hb + a * AST + j0]);
            u64 h1 = dup2(sm[hb + a * AST + j0 + 1]);
            u64 g01, g23;
            lds_v2u64(&sm[gb + a * AST + k0], g01, g23);
            fma2(acc[0][0], h0, g01); fma2(acc[0][1], h0, g23);
            fma2(acc[1][0], h1, g01); fma2(acc[1][1], h1, g23);
        }
        #pragma unroll
        for (int r = 0; r < 2; ++r) {
            float l0, l1, l2, l3;
            upk2(acc[r][0], l0, l1); upk2(acc[r][1], l2, l3);
            *(float4*)&sm[OFF_LT + p * 400 + (j0 + r) * 20 + k0] =
                make_float4(l0, l1, l2, l3);
        }
    } else if (tid < 280) {
        int idx = tid - 200;                 // (pixel, k)
        int p = idx / 20, k = idx % 20;
        float acc = 0.f;
        #pragma unroll 8
        for (int b = 0; b < 64; ++b)
            acc += sm[OFF_V + b] * sm[OFF_A2 + b * AST + p * 20 + k];
        sm[OFF_VH + idx] = acc;
    }
    __syncthreads();

    // ---- softmax over k per (pixel, j), att back into LT[p][j][k] ----
    if (tid < PPB * J_) {
        int p = tid / J_, j = tid % J_;
        int lb = OFF_LT + p * 400 + j * 20;
        float l[J_];
        float mx = -1e30f;
        #pragma unroll
        for (int k = 0; k < J_; ++k) {
            l[k] = sm[lb + k] + sm[OFF_VH + p * 20 + k];
            mx = fmaxf(mx, l[k]);
        }
        float sum = 0.f;
        #pragma unroll
        for (int k = 0; k < J_; ++k) { l[k] = __expf(l[k] - mx); sum += l[k]; }
        float inv = 1.f / sum;
        #pragma unroll
        for (int k = 0; k < J_; ++k) sm[lb + k] = l[k] * inv;
    }
    __syncthreads();

    // ---- AGG[c][j*4+p] = sum_k H[c][p*20+k] * att[p][j][k]   -> A1 ----
    {
        int jg = tid % 5;                 // j0 = jg*4
        int p  = (tid / 5) & 3;
        int c0 = (tid / 20) * 4;          // 0..60
        float acc[4][4] = {};
        int hb = OFF_A2 + p * 20;
        int ab = OFF_LT + p * 400;
        #pragma unroll
        for (int k = 0; k < J_; ++k) {
            float h[4], a[4];
            #pragma unroll
            for (int i = 0; i < 4; ++i) h[i] = sm[hb + (c0 + i) * AST + k];
            #pragma unroll
            for (int r = 0; r < 4; ++r) a[r] = sm[ab + (jg * 4 + r) * 20 + k];
            #pragma unroll
            for (int i = 0; i < 4; ++i)
                #pragma unroll
                for (int r = 0; r < 4; ++r)
                    acc[i][r] += h[i] * a[r];
        }
        #pragma unroll
        for (int i = 0; i < 4; ++i)
            #pragma unroll
            for (int r = 0; r < 4; ++r)
                sm[OFF_A1 + (c0 + i) * AST + (jg * 4 + r) * 4 + p] = acc[i][r];
    }
    __syncthreads();

    // ---- OUT GEMM: out[o][j, 4 pixels] = sum_c W[c][o] * AGG[c][j*4+p] ----
    {
        u64 acc[4][2];
        #pragma unroll
        for (int i = 0; i < 4; ++i) { acc[i][0] = 0ull; acc[i][1] = 0ull; }
        #pragma unroll 8
        for (int c = 0; c < 64; ++c) {
            float4 w = *(const float4*)&sm[OFF_WW + c * 64 + d0];
            u64 a01, a23;
            lds_v2u64(&sm[OFF_A1 + c * AST + col0], a01, a23);
            #pragma unroll
            for (int i = 0; i < 4; ++i) {
                u64 wd = dup2((&w.x)[i]);
                fma2(acc[i][0], wd, a01);
                fma2(acc[i][1], wd, a23);
            }
        }
        if (cg < J_) {
            int b    = pix0 / 2560;
            int poff = pix0 % 2560;
            #pragma unroll
            for (int i = 0; i < 4; ++i) {
                float v0, v1, v2, v3;
                upk2(acc[i][0], v0, v1); upk2(acc[i][1], v2, v3);
                *(float4*)&out[((size_t)((b * 64 + d0 + i) * J_ + cg)) * 2560 + poff] =
                    make_float4(v0, v1, v2, v3);
            }
        }
    }
}

// ------------------------------ launcher --------------------------------------
extern "C" void kernel_launch(void* const* d_in, const int* in_sizes, int n_in,
                              void* d_out, int out_size) {
    const float* x     = (const float*)d_in[0];
    const float* gamma = (const float*)d_in[1];
    const float* beta  = (const float*)d_in[2];
    const float* w1    = (const float*)d_in[3];
    const float* b1    = (const float*)d_in[4];
    const float* w2    = (const float*)d_in[5];
    const float* b2    = (const float*)d_in[6];
    const float* ws1   = (const float*)d_in[7];
    const float* bs1   = (const float*)d_in[8];
    const float* ws2   = (const float*)d_in[9];
    // d_in[10] = bs2 (softmax-invariant), d_in[11] = W
    const float* W     = (const float*)d_in[11];
    float* out = (float*)d_out;

    cudaFuncSetAttribute(geo_gcn_main_kernel,
                         cudaFuncAttributeMaxDynamicSharedMemorySize, SMEM_BYTES);

    bn_stats_kernel<<<NCH / 8, 256>>>(x, gamma, beta);
    setup_kernel<<<16, 256>>>(w1, w2, ws1, bs1, ws2);
    xn_kernel<<<B_ * 32, 256>>>(x);
    geo_gcn_main_kernel<<<NPIX / PPB, NTH, SMEM_BYTES>>>(b1, b2, W, out);
}